// round 4
// baseline (speedup 1.0000x reference)
#include <cuda_runtime.h>
#include <cuda_bf16.h>

// ---------------- problem constants ----------------
#define NNODES 100000
#define NEDGES 1600000
#define IND    128
#define HD     64
#define EDD    64
#define NLAYER 3
#define OUTD   3

#define TE     128            // edges per tile
#define NTHR   256            // threads per block (8 warps)
#define NTILES (NEDGES / TE)  // 12500

// ---------------- device scratch (static globals; no allocations) ----------------
__device__ float g_h  [(size_t)NNODES * HD];    // node features
__device__ float g_agg[(size_t)NNODES * HD];    // scatter accumulator
__device__ float g_ea [(size_t)NEDGES * EDD];   // edge features between layers
__device__ float g_pool[HD];                    // pooled sums

// ---------------- f32x2 helpers ----------------
#define FMA2(acc, a, b) \
    asm("fma.rn.f32x2 %0, %1, %2, %0;" : "+l"(acc) : "l"(a), "l"(b))
#define PACK2(d, x, y) \
    asm("mov.b64 %0, {%1, %2};" : "=l"(d) : "f"(x), "f"(y))
#define DUP2(d, x) \
    asm("mov.b64 %0, {%1, %1};" : "=l"(d) : "f"(x))
#define UNPACK2(x, y, d) \
    asm("mov.b64 {%0, %1}, %2;" : "=f"(x), "=f"(y) : "l"(d))

typedef unsigned long long ull;

// ---------------- fused edge-layer kernel ----------------
// smem carve (floats):
//   sHrow [64][128]   0
//   sHcol [64][128]   8192
//   sEA   [64][128]   16384
//   sT    [64][128]   24576
//   sW    [192][64]   32768  (12288 floats)
//   sRow/sCol ints    45056  (256 ints)
#define SMEM_EDGE_FLOATS (45056 + 256)
#define SMEM_EDGE_BYTES  (SMEM_EDGE_FLOATS * 4)

__device__ __forceinline__ void stage_w(const float* __restrict__ g, float* __restrict__ s,
                                        int nfloat, int tid) {
    const float4* gs = (const float4*)g;
    float4* ss = (float4*)s;
    int n4 = nfloat >> 2;
    for (int i = tid; i < n4; i += NTHR) ss[i] = gs[i];
}

// gather 32 consecutive floats from src into k-major dst column (stride 128)
__device__ __forceinline__ void gather_row(const float* __restrict__ src, float* __restrict__ dst) {
#pragma unroll
    for (int i = 0; i < 8; i++) {
        float4 v = ((const float4*)src)[i];
        dst[(4 * i + 0) * TE] = v.x;
        dst[(4 * i + 1) * TE] = v.y;
        dst[(4 * i + 2) * TE] = v.z;
        dst[(4 * i + 3) * TE] = v.w;
    }
}

__device__ __forceinline__ void init_acc(ull acc[4][4], const float* __restrict__ bias, int wid) {
    float4 b0 = *(const float4*)(bias + 8 * wid);
    float4 b1 = *(const float4*)(bias + 8 * wid + 4);
    ull bb[4];
    PACK2(bb[0], b0.x, b0.y);
    PACK2(bb[1], b0.z, b0.w);
    PACK2(bb[2], b1.x, b1.y);
    PACK2(bb[3], b1.z, b1.w);
#pragma unroll
    for (int i = 0; i < 4; i++)
#pragma unroll
        for (int p = 0; p < 4; p++) acc[i][p] = bb[p];
}

// accumulate one 64-k chunk: acc[edge i][out-pair p] += A[k][e] * W[k][o]
__device__ __forceinline__ void accum_chunk(const float* __restrict__ sA,
                                            const float* __restrict__ sWc,
                                            int a_off /*4*lane*/, int w_off /*8*wid*/,
                                            ull acc[4][4]) {
#pragma unroll 4
    for (int k = 0; k < 64; k++) {
        float4 av = *(const float4*)(sA + k * TE + a_off);
        ulonglong2 wa = *(const ulonglong2*)(sWc + k * 64 + w_off);
        ulonglong2 wb = *(const ulonglong2*)(sWc + k * 64 + w_off + 4);
        ull d0, d1, d2, d3;
        DUP2(d0, av.x); DUP2(d1, av.y); DUP2(d2, av.z); DUP2(d3, av.w);
        FMA2(acc[0][0], d0, wa.x); FMA2(acc[0][1], d0, wa.y);
        FMA2(acc[0][2], d0, wb.x); FMA2(acc[0][3], d0, wb.y);
        FMA2(acc[1][0], d1, wa.x); FMA2(acc[1][1], d1, wa.y);
        FMA2(acc[1][2], d1, wb.x); FMA2(acc[1][3], d1, wb.y);
        FMA2(acc[2][0], d2, wa.x); FMA2(acc[2][1], d2, wa.y);
        FMA2(acc[2][2], d2, wb.x); FMA2(acc[2][3], d2, wb.y);
        FMA2(acc[3][0], d3, wa.x); FMA2(acc[3][1], d3, wa.y);
        FMA2(acc[3][2], d3, wb.x); FMA2(acc[3][3], d3, wb.y);
    }
}

template <bool RELU>
__device__ __forceinline__ void epilogue_store(ull acc[4][4], float* __restrict__ sDst,
                                               int lane, int wid) {
#pragma unroll
    for (int p = 0; p < 4; p++) {
        float lo[4], hi[4];
#pragma unroll
        for (int i = 0; i < 4; i++) {
            UNPACK2(lo[i], hi[i], acc[i][p]);
            if (RELU) { lo[i] = fmaxf(lo[i], 0.f); hi[i] = fmaxf(hi[i], 0.f); }
        }
        *(float4*)(sDst + (8 * wid + 2 * p + 0) * TE + 4 * lane) = make_float4(lo[0], lo[1], lo[2], lo[3]);
        *(float4*)(sDst + (8 * wid + 2 * p + 1) * TE + 4 * lane) = make_float4(hi[0], hi[1], hi[2], hi[3]);
    }
}

__device__ __forceinline__ void red_v4(float* p, float a, float b, float c, float d) {
    asm volatile("red.global.add.v4.f32 [%0], {%1, %2, %3, %4};"
                 :: "l"(p), "f"(a), "f"(b), "f"(c), "f"(d) : "memory");
}

__global__ void __launch_bounds__(NTHR, 1)
edge_kernel(const int* __restrict__ ei, const float* __restrict__ ea_in,
            const float* __restrict__ W1, const float* __restrict__ B1,
            const float* __restrict__ W2, const float* __restrict__ B2,
            const float* __restrict__ W3, const float* __restrict__ B3,
            const float* __restrict__ W4, const float* __restrict__ B4,
            int write_ea) {
    extern __shared__ float sm[];
    float* sHrow = sm;
    float* sHcol = sm + 8192;
    float* sEA   = sm + 16384;
    float* sT    = sm + 24576;
    float* sW    = sm + 32768;
    int*   sRow  = (int*)(sm + 45056);
    int*   sCol  = sRow + TE;

    const int tid  = threadIdx.x;
    const int lane = tid & 31;
    const int wid  = tid >> 5;
    const long long e0 = (long long)blockIdx.x * TE;

    if (tid < TE) {
        // edge_index is int32 (JAX default x64-disabled coerces jnp.int64 -> int32)
        sRow[tid] = ei[e0 + tid];
        sCol[tid] = ei[(long long)NEDGES + e0 + tid];
    }
    __syncthreads();

    // gather h[row], h[col], ea  (2 threads per edge) + stage W1 (192x64)
    {
        int e = tid >> 1, half = tid & 1;
        int r = sRow[e], c = sCol[e];
        gather_row(g_h + (size_t)r * HD + 32 * half, sHrow + half * 32 * TE + e);
        gather_row(g_h + (size_t)c * HD + 32 * half, sHcol + half * 32 * TE + e);
        gather_row(ea_in + (size_t)(e0 + e) * EDD + 32 * half, sEA + half * 32 * TE + e);
    }
    stage_w(W1, sW, 192 * 64, tid);
    __syncthreads();

    ull acc[4][4];
    const int a_off = lane << 2, w_off = wid << 3;

    // GEMM1: relu([hrow,hcol,ea] @ W1 + B1) -> sT
    init_acc(acc, B1, wid);
    accum_chunk(sHrow, sW,            a_off, w_off, acc);
    accum_chunk(sHcol, sW + 64 * 64,  a_off, w_off, acc);
    accum_chunk(sEA,   sW + 128 * 64, a_off, w_off, acc);
    epilogue_store<true>(acc, sT, lane, wid);
    __syncthreads();

    // GEMM2: sT @ W2 + B2 -> sEA (new edge features)
    stage_w(W2, sW, 64 * 64, tid);
    __syncthreads();
    init_acc(acc, B2, wid);
    accum_chunk(sT, sW, a_off, w_off, acc);
    epilogue_store<false>(acc, sEA, lane, wid);
    __syncthreads();

    // GEMM3: relu([hrow, ea_new] @ W3 + B3) -> sT
    stage_w(W3, sW, 128 * 64, tid);
    __syncthreads();
    init_acc(acc, B3, wid);
    accum_chunk(sHrow, sW,           a_off, w_off, acc);
    accum_chunk(sEA,   sW + 64 * 64, a_off, w_off, acc);
    epilogue_store<true>(acc, sT, lane, wid);
    __syncthreads();

    // GEMM4: msg = sT @ W4 + B4 -> scatter-add into g_agg[col]
    stage_w(W4, sW, 64 * 64, tid);
    __syncthreads();
    init_acc(acc, B4, wid);
    accum_chunk(sT, sW, a_off, w_off, acc);

    float v[4][8];
#pragma unroll
    for (int p = 0; p < 4; p++)
#pragma unroll
        for (int i = 0; i < 4; i++) UNPACK2(v[i][2 * p], v[i][2 * p + 1], acc[i][p]);
#pragma unroll
    for (int i = 0; i < 4; i++) {
        int c = sCol[4 * lane + i];
        float* p = g_agg + (size_t)c * HD + 8 * wid;
        red_v4(p,     v[i][0], v[i][1], v[i][2], v[i][3]);
        red_v4(p + 4, v[i][4], v[i][5], v[i][6], v[i][7]);
    }

    // persist new edge features for next layer (coalesced via smem transpose)
    if (write_ea) {
        int e = tid >> 1, half = tid & 1;
        const float* src = sEA + half * 32 * TE + e;
        float4* dst = (float4*)(g_ea + (size_t)(e0 + e) * EDD + 32 * half);
#pragma unroll
        for (int i = 0; i < 8; i++) {
            float4 w;
            w.x = src[(4 * i + 0) * TE];
            w.y = src[(4 * i + 1) * TE];
            w.z = src[(4 * i + 2) * TE];
            w.w = src[(4 * i + 3) * TE];
            dst[i] = w;
        }
    }
}

// ---------------- node projection: h = x @ pW + pb ; agg = 0 ----------------
// 32 nodes / block, grid 3125. smem: xs[32][132] + sWp[128][64]
#define SMEM_PROJ_FLOATS (32 * 132 + 128 * 64)
#define SMEM_PROJ_BYTES  (SMEM_PROJ_FLOATS * 4)

__global__ void __launch_bounds__(NTHR, 1)
proj_kernel(const float* __restrict__ x, const float* __restrict__ pW,
            const float* __restrict__ pb) {
    extern __shared__ float sm[];
    float* xs  = sm;            // [32][132]
    float* sWp = sm + 32 * 132; // [128][64]
    int tid = threadIdx.x;
    int nb0 = blockIdx.x * 32;

    // stage x tile (4096 floats) with pad-132 rows
    {
        const float4* gx = (const float4*)(x + (size_t)nb0 * IND);
        for (int i = tid; i < 1024; i += NTHR) {
            float4 vv = gx[i];
            *(float4*)(xs + (i >> 5) * 132 + ((i & 31) << 2)) = vv;
        }
    }
    // stage weights (8192 floats)
    {
        const float4* gw = (const float4*)pW;
        float4* sw = (float4*)sWp;
        for (int i = tid; i < 2048; i += NTHR) sw[i] = gw[i];
    }
    __syncthreads();

    int node = tid >> 3, g = tid & 7;
    float a0[8];
    float4 b0 = *(const float4*)(pb + 8 * g);
    float4 b1 = *(const float4*)(pb + 8 * g + 4);
    a0[0] = b0.x; a0[1] = b0.y; a0[2] = b0.z; a0[3] = b0.w;
    a0[4] = b1.x; a0[5] = b1.y; a0[6] = b1.z; a0[7] = b1.w;
#pragma unroll 4
    for (int k = 0; k < IND; k++) {
        float a = xs[node * 132 + k];
        float4 w0 = *(const float4*)(sWp + k * 64 + 8 * g);
        float4 w1 = *(const float4*)(sWp + k * 64 + 8 * g + 4);
        a0[0] = fmaf(a, w0.x, a0[0]); a0[1] = fmaf(a, w0.y, a0[1]);
        a0[2] = fmaf(a, w0.z, a0[2]); a0[3] = fmaf(a, w0.w, a0[3]);
        a0[4] = fmaf(a, w1.x, a0[4]); a0[5] = fmaf(a, w1.y, a0[5]);
        a0[6] = fmaf(a, w1.z, a0[6]); a0[7] = fmaf(a, w1.w, a0[7]);
    }
    size_t base = (size_t)(nb0 + node) * HD + 8 * g;
    *(float4*)(g_h + base)     = make_float4(a0[0], a0[1], a0[2], a0[3]);
    *(float4*)(g_h + base + 4) = make_float4(a0[4], a0[5], a0[6], a0[7]);
    *(float4*)(g_agg + base)     = make_float4(0.f, 0.f, 0.f, 0.f);
    *(float4*)(g_agg + base + 4) = make_float4(0.f, 0.f, 0.f, 0.f);
}

// ---------------- node update: h = relu(agg + h); agg = 0; (also zero g_pool) --------
__global__ void node_update_kernel() {
    size_t i = (size_t)blockIdx.x * NTHR + threadIdx.x;  // float4 index, 1.6M total
    float4* h4 = (float4*)g_h;
    float4* a4 = (float4*)g_agg;
    float4 h = h4[i], a = a4[i];
    h.x = fmaxf(h.x + a.x, 0.f);
    h.y = fmaxf(h.y + a.y, 0.f);
    h.z = fmaxf(h.z + a.z, 0.f);
    h.w = fmaxf(h.w + a.w, 0.f);
    h4[i] = h;
    a4[i] = make_float4(0.f, 0.f, 0.f, 0.f);
    if (blockIdx.x == 0 && threadIdx.x < HD) g_pool[threadIdx.x] = 0.f;
}

// ---------------- pooling: g_pool[k] = sum_n h[n][k] ----------------
__global__ void pool_kernel() {
    __shared__ float sP[NTHR];
    int tid = threadIdx.x;
    int k = tid & 63, sub = tid >> 6;
    int n0 = blockIdx.x * 256 + sub * 64;
    float s = 0.f;
#pragma unroll 4
    for (int i = 0; i < 64; i++) {
        int n = n0 + i;
        if (n < NNODES) s += g_h[(size_t)n * HD + k];
    }
    sP[tid] = s;
    __syncthreads();
    if (tid < 64) {
        float t = sP[tid] + sP[tid + 64] + sP[tid + 128] + sP[tid + 192];
        atomicAdd(&g_pool[tid], t);
    }
}

// ---------------- final: out = mean(h) @ lW + lb ----------------
__global__ void final_kernel(const float* __restrict__ lW, const float* __restrict__ lb,
                             float* __restrict__ out) {
    int o = threadIdx.x;
    if (o < OUTD) {
        const float invN = 1.0f / (float)NNODES;
        float s = lb[o];
        for (int k = 0; k < HD; k++) s = fmaf(g_pool[k] * invN, lW[k * OUTD + o], s);
        out[o] = s;
    }
}

// ---------------- launch ----------------
extern "C" void kernel_launch(void* const* d_in, const int* in_sizes, int n_in,
                              void* d_out, int out_size) {
    const float* x   = (const float*)d_in[0];
    const int*   ei  = (const int*)d_in[1];       // int32 (JAX x64 disabled)
    const float* ea  = (const float*)d_in[2];
    const float* pW  = (const float*)d_in[3];
    const float* pb  = (const float*)d_in[4];
    const float* eW1 = (const float*)d_in[5];
    const float* eb1 = (const float*)d_in[6];
    const float* eW2 = (const float*)d_in[7];
    const float* eb2 = (const float*)d_in[8];
    const float* nW1 = (const float*)d_in[9];
    const float* nb1 = (const float*)d_in[10];
    const float* nW2 = (const float*)d_in[11];
    const float* nb2 = (const float*)d_in[12];
    const float* lW  = (const float*)d_in[13];
    const float* lb  = (const float*)d_in[14];
    float* out = (float*)d_out;

    cudaFuncSetAttribute(edge_kernel, cudaFuncAttributeMaxDynamicSharedMemorySize, SMEM_EDGE_BYTES);
    cudaFuncSetAttribute(proj_kernel, cudaFuncAttributeMaxDynamicSharedMemorySize, SMEM_PROJ_BYTES);

    float* g_ea_ptr;
    cudaGetSymbolAddress((void**)&g_ea_ptr, g_ea);

    proj_kernel<<<NNODES / 32, NTHR, SMEM_PROJ_BYTES>>>(x, pW, pb);

    for (int l = 0; l < NLAYER; l++) {
        const float* ea_in = (l == 0) ? ea : (const float*)g_ea_ptr;
        edge_kernel<<<NTILES, NTHR, SMEM_EDGE_BYTES>>>(
            ei, ea_in,
            eW1 + (size_t)l * 192 * 64, eb1 + l * 64,
            eW2 + (size_t)l * 64 * 64,  eb2 + l * 64,
            nW1 + (size_t)l * 128 * 64, nb1 + l * 64,
            nW2 + (size_t)l * 64 * 64,  nb2 + l * 64,
            (l < NLAYER - 1) ? 1 : 0);
        node_update_kernel<<<(NNODES * HD) / (4 * NTHR), NTHR>>>();
    }

    pool_kernel<<<(NNODES + 255) / 256, NTHR>>>();
    final_kernel<<<1, 32>>>(lW, lb, out);
}